// round 12
// baseline (speedup 1.0000x reference)
#include <cuda_runtime.h>
#include <cstdint>
#include <math.h>

#define BB 8192
#define KD 256     // complex dim K
#define MD 1024    // sparse dim M
#define TT 10

#define LDA 36               // padded smem row stride (floats)
#define TSZ (128 * LDA)      // one tile (floats)
#define SMEM_BYTES (4 * TSZ * 4)   // 73728 (A/X x 2 stages)

// ---------------- scratch ----------------
__device__ __align__(16) float g_x[BB * 512];           // x    [b][2K]
__device__ __align__(16) float g_xmap[BB * 512];        // xmap [b][2K]
__device__ __align__(16) float g_b0[BB * 512];          // b0   [b][2K]
__device__ __align__(16) float g_xsp[(size_t)BB * MD];  // xsp  [b][M]
__device__ __align__(16) float g_eb0[(size_t)BB * MD];  // Eb0  [b][M]
__device__ __align__(16) float g_R[512 * 512];
__device__ __align__(16) float g_RT[512 * 512];         // R^T
__device__ __align__(16) float g_WXr[512 * 256];
__device__ __align__(16) float g_E[MD * 512];
__device__ __align__(16) float g_ER[MD * 512];          // E.R  [m][k']
__device__ __align__(16) float g_D[512 * MD];
__device__ __align__(16) float g_S[9 * 1536 * 512];     // [U_i; M_i] for i=2..10
__device__ __align__(16) float g_acc[3];

// ---------------- asm helpers ----------------
__device__ __forceinline__ uint32_t smem_u32(const void* p) {
    uint32_t a;
    asm("{ .reg .u64 t; cvta.to.shared.u64 t, %1; cvt.u32.u64 %0, t; }" : "=r"(a) : "l"(p));
    return a;
}
__device__ __forceinline__ void cp16(uint32_t dst, const void* src) {
    asm volatile("cp.async.cg.shared.global [%0], [%1], 16;" :: "r"(dst), "l"(src));
}
__device__ __forceinline__ void cp_commit() {
    asm volatile("cp.async.commit_group;" ::: "memory");
}
template <int N>
__device__ __forceinline__ void cp_wait() {
    asm volatile("cp.async.wait_group %0;" :: "n"(N) : "memory");
}
__device__ __forceinline__ void mma8(float* c, uint32_t a0, uint32_t a1, uint32_t a2, uint32_t a3,
                                     uint32_t b0, uint32_t b1) {
    asm volatile(
        "mma.sync.aligned.m16n8k8.row.col.f32.tf32.tf32.f32 "
        "{%0,%1,%2,%3}, {%4,%5,%6,%7}, {%8,%9}, {%0,%1,%2,%3};"
        : "+f"(c[0]), "+f"(c[1]), "+f"(c[2]), "+f"(c[3])
        : "r"(a0), "r"(a1), "r"(a2), "r"(a3), "r"(b0), "r"(b1));
}
// hi = rna-tf32(v); lo = raw residual (MMA truncates tail; ~2^-21, negligible)
__device__ __forceinline__ void split1(float v, uint32_t& h, uint32_t& l) {
    uint32_t hb;
    asm("cvt.rna.tf32.f32 %0, %1;" : "=r"(hb) : "f"(v));
    h = hb;
    l = __float_as_uint(v - __uint_as_float(hb));
}

// ---------------- tf32x3 GEMM: D[m][b] = A[m][:] . X[b][:] ----------------
// EPI 0: plain store               (ER, Eb0)
// EPI 1: OUT=d, OUT2=scalA*d      (b0 + x1 fused)
// EPI 2: fused update+encode: m0<512 -> x = d + gam*b0 ; m0>=512 -> shrink(d + gam*Eb0)
// EPI 3: decode: xmap=d, huber(aux1, d)
template <int KIN, int MOUT, int EPI>
__global__ void __launch_bounds__(256, 2) k_gemm(
    const float* __restrict__ A, const float* __restrict__ Xm,
    float* __restrict__ OUT, float* __restrict__ OUT2,
    const float* __restrict__ aux1, const float* __restrict__ aux2,
    const float* __restrict__ aux3,
    const float* __restrict__ scalA, const float* __restrict__ scalB, int last)
{
    extern __shared__ float sm[];
    float* As = sm;             // [2][128][LDA]
    float* Xs = sm + 2 * TSZ;   // [2][128][LDA]

    const int tid = threadIdx.x;
    const int wid = tid >> 5, lane = tid & 31;
    const int g = lane >> 2, tg = lane & 3;
    const int b0 = blockIdx.x * 128;
    const int m0 = blockIdx.y * 128;
    const int m_off = (wid & 1) * 64;
    const int n_off = (wid >> 1) * 32;

    constexpr int NS = KIN / 32;

    const int crow = tid >> 3, ccg = (tid & 7) * 4;

    auto issue = [&](int st) {
        const int kk = st * 32;
        float* Ao = As + (st & 1) * TSZ;
        float* Xo = Xs + (st & 1) * TSZ;
#pragma unroll
        for (int r = 0; r < 4; r++) {
            int rr = crow + 32 * r;
            cp16(smem_u32(Ao + rr * LDA + ccg), A + (size_t)(m0 + rr) * KIN + kk + ccg);
            cp16(smem_u32(Xo + rr * LDA + ccg), Xm + (size_t)(b0 + rr) * KIN + kk + ccg);
        }
        cp_commit();
    };

    float c[4][4][4];
#pragma unroll
    for (int i = 0; i < 4; i++)
#pragma unroll
        for (int j = 0; j < 4; j++)
#pragma unroll
            for (int q = 0; q < 4; q++) c[i][j][q] = 0.f;

    issue(0);
    issue(1);

    for (int kt = 0; kt < NS; kt++) {
        cp_wait<1>();
        __syncthreads();

        const int buf = kt & 1;
        const float* Ab = As + buf * TSZ;
        const float* Xb = Xs + buf * TSZ;
#pragma unroll
        for (int ks = 0; ks < 4; ks++) {
            const float* ap = Ab + (m_off + g) * LDA + ks * 8 + tg;
            const float* xp = Xb + (n_off + g) * LDA + ks * 8 + tg;
            uint32_t ah[4][4], al[4][4], xh[4][2], xl[4][2];
#pragma unroll
            for (int mf = 0; mf < 4; mf++) {
                split1(ap[mf * 16 * LDA],               ah[mf][0], al[mf][0]);
                split1(ap[mf * 16 * LDA + 8 * LDA],     ah[mf][1], al[mf][1]);
                split1(ap[mf * 16 * LDA + 4],           ah[mf][2], al[mf][2]);
                split1(ap[mf * 16 * LDA + 8 * LDA + 4], ah[mf][3], al[mf][3]);
            }
#pragma unroll
            for (int nf = 0; nf < 4; nf++) {
                split1(xp[nf * 8 * LDA],     xh[nf][0], xl[nf][0]);
                split1(xp[nf * 8 * LDA + 4], xh[nf][1], xl[nf][1]);
            }
#pragma unroll
            for (int mf = 0; mf < 4; mf++)
#pragma unroll
                for (int nf = 0; nf < 4; nf++) {
                    mma8(c[mf][nf], ah[mf][0], ah[mf][1], ah[mf][2], ah[mf][3], xh[nf][0], xh[nf][1]);
                    mma8(c[mf][nf], ah[mf][0], ah[mf][1], ah[mf][2], ah[mf][3], xl[nf][0], xl[nf][1]);
                    mma8(c[mf][nf], al[mf][0], al[mf][1], al[mf][2], al[mf][3], xh[nf][0], xh[nf][1]);
                }
        }
        __syncthreads();
        if (kt + 2 < NS) issue(kt + 2);
        else cp_commit();
    }

    // ---------------- epilogue ----------------
    float s_a = 0.f, s_b = 0.f;
    float gam = 0.f, eta = 0.f;
    if (EPI == 1 || EPI == 2) gam = scalA[0];
    if (EPI == 2) eta = scalB[0];
#pragma unroll
    for (int mf = 0; mf < 4; mf++)
#pragma unroll
        for (int nf = 0; nf < 4; nf++) {
#pragma unroll
            for (int q = 0; q < 4; q++) {
                int m = m0 + m_off + mf * 16 + g + (q >= 2 ? 8 : 0);
                int b = b0 + n_off + nf * 8 + tg * 2 + (q & 1);
                float d = c[mf][nf][q];
                if (EPI == 0) {
                    OUT[(size_t)b * MOUT + m] = d;
                } else if (EPI == 1) {
                    size_t o = (size_t)b * MOUT + m;
                    OUT[o] = d;
                    OUT2[o] = gam * d;
                } else if (EPI == 2) {
                    if (m0 < 512) {                        // x-part: U_i.xmap + gam*b0
                        size_t o = (size_t)b * 512 + m;
                        OUT[o] = d + gam * aux2[o];
                    } else {                               // z-part: M_i.xmap + gam*Eb0 -> shrink
                        size_t o = (size_t)b * 1024 + (m - 512);
                        float z = d + gam * aux3[o];
                        float ad = fabsf(z) - eta;
                        float v = (ad > 0.f) ? copysignf(ad, z) : 0.f;
                        OUT2[o] = v;
                        s_a += fabsf(v);
                        if (last) s_b += (fabsf(v) > 1e-3f) ? 1.f : 0.f;
                    }
                } else {                                   // decode + huber
                    size_t o = (size_t)b * MOUT + m;
                    float xo = aux1[o];
                    float dd = xo - d; float ad = fabsf(dd);
                    s_a += (ad < 1.f) ? 0.5f * dd * dd : ad - 0.5f;
                    OUT[o] = d;
                }
            }
        }
    if (EPI == 3 || (EPI == 2 && m0 >= 512)) {
#pragma unroll
        for (int off = 16; off > 0; off >>= 1) {
            s_a += __shfl_down_sync(0xffffffffu, s_a, off);
            if (EPI == 2) s_b += __shfl_down_sync(0xffffffffu, s_b, off);
        }
        if (lane == 0) {
            atomicAdd(&g_acc[EPI == 2 ? 0 : 1], s_a);
            if (EPI == 2 && last) atomicAdd(&g_acc[2], s_b);
        }
    }
}

// ---------------- prep kernels ----------------
__global__ void k_zero() { if (threadIdx.x < 3) g_acc[threadIdx.x] = 0.f; }

// R + R^T from WX*W
__global__ void k_prep_R(const float* __restrict__ W, const float* __restrict__ WX) {
    int j = blockIdx.x * 16 + threadIdx.x;
    int i = blockIdx.y * 16 + threadIdx.y;
    float pre = 0.f, pim = 0.f;
#pragma unroll 4
    for (int n = 0; n < 128; n++) {
        float ar = WX[i * 128 + n], ai = WX[32768 + i * 128 + n];
        float br = W[n * 256 + j],  bi = W[32768 + n * 256 + j];
        pre += ar * br - ai * bi;
        pim += ar * bi + ai * br;
    }
    g_R[i * 512 + j] = pre;
    g_R[i * 512 + j + 256] = -pim;
    g_R[(i + 256) * 512 + j] = pim;
    g_R[(i + 256) * 512 + j + 256] = pre;
    g_RT[j * 512 + i] = pre;
    g_RT[(j + 256) * 512 + i] = -pim;
    g_RT[j * 512 + i + 256] = pim;
    g_RT[(j + 256) * 512 + i + 256] = pre;
}

__global__ void k_prepB(const float* __restrict__ E0, const float* __restrict__ WX) {
    size_t idx = (size_t)blockIdx.x * 256 + threadIdx.x;
    if (idx < 131072) {                           // WXr [512][256]
        int np = (int)idx & 255, j = (int)idx >> 8;
        int jj = j & 255, jr = j >> 8;
        int nn = np & 127, nc = np >> 7;
        float re = WX[jj * 128 + nn], im = WX[32768 + jj * 128 + nn];
        g_WXr[idx] = (jr == 0) ? ((nc == 0) ? re : -im) : ((nc == 0) ? im : re);
    } else if (idx < 131072 + 524288) {           // E [1024][512]
        size_t t = idx - 131072;
        int k = (int)t & 511, mrow = (int)(t >> 9);
        g_E[t] = (k < 256) ? E0[mrow * 256 + k] : -E0[262144 + mrow * 256 + (k - 256)];
    } else {                                      // D [512][1024]
        size_t t = idx - 131072 - 524288;
        int mrow = (int)t & 1023, j = (int)(t >> 10);
        g_D[t] = (j < 256) ? E0[mrow * 256 + j] : -E0[262144 + mrow * 256 + (j - 256)];
    }
}

// S_i = [I - g_i R ; E - g_i ER] for i=2..10
__global__ void k_build_S(const float* __restrict__ gammas) {
    size_t idx = (size_t)blockIdx.x * 256 + threadIdx.x;   // 9*1536*512
    if (idx >= 9ull * 1536 * 512) return;
    int k = (int)(idx & 511);
    int m = (int)((idx >> 9) % 1536);
    int i2 = (int)(idx / (1536 * 512));
    float gamv = gammas[i2 + 2];
    float v;
    if (m < 512) v = ((m == k) ? 1.f : 0.f) - gamv * g_R[m * 512 + k];
    else         v = g_E[(m - 512) * 512 + k] - gamv * g_ER[(m - 512) * 512 + k];
    g_S[idx] = v;
}

// iteration 1 encode: xsp = shrink(g1*Eb0, eta1), + L1
__global__ void k_shrink1(const float* __restrict__ gammas, const float* __restrict__ etas) {
    size_t idx = (size_t)blockIdx.x * 256 + threadIdx.x;   // BB*MD
    float gamv = gammas[1], eta = etas[1];
    float z = gamv * g_eb0[idx];
    float ad = fabsf(z) - eta;
    float v = (ad > 0.f) ? copysignf(ad, z) : 0.f;
    g_xsp[idx] = v;
    float s = fabsf(v);
#pragma unroll
    for (int off = 16; off > 0; off >>= 1) s += __shfl_down_sync(0xffffffffu, s, off);
    if ((threadIdx.x & 31) == 0) atomicAdd(&g_acc[0], s);
}

__global__ void k_final(float* __restrict__ out) {
    int idx = blockIdx.x * 256 + threadIdx.x;
    int k = idx & 255, b = (idx >> 8) & 8191, cch = idx >> 21;
    out[idx] = g_xmap[(size_t)b * 512 + cch * 256 + k];
}

__global__ void k_scalars(float* __restrict__ out) {
    if (threadIdx.x == 0 && blockIdx.x == 0) {
        size_t base = 2ull * BB * KD;
        out[base + 0] = g_acc[0] / (float)BB;
        out[base + 1] = g_acc[1] / ((float)2 * KD * BB * TT);
        out[base + 2] = g_acc[2] / (float)BB;
    }
}

// ---------------- launch ----------------
extern "C" void kernel_launch(void* const* d_in, const int* in_sizes, int n_in,
                              void* d_out, int out_size) {
    const float* y      = (const float*)d_in[0];
    const float* W      = (const float*)d_in[1];
    const float* WX     = (const float*)d_in[2];
    const float* E0     = (const float*)d_in[3];
    const float* etas   = (const float*)d_in[4];
    const float* gammas = (const float*)d_in[5];
    float* out = (float*)d_out;

    void *p;
    cudaGetSymbolAddress(&p, g_R);    const float* fR   = (const float*)p;
    cudaGetSymbolAddress(&p, g_RT);   const float* fRT  = (const float*)p;
    cudaGetSymbolAddress(&p, g_WXr);  const float* fWXr = (const float*)p;
    cudaGetSymbolAddress(&p, g_E);    const float* fE   = (const float*)p;
    cudaGetSymbolAddress(&p, g_ER);   float* fER = (float*)p;
    cudaGetSymbolAddress(&p, g_D);    const float* fD   = (const float*)p;
    cudaGetSymbolAddress(&p, g_S);    const float* fS   = (const float*)p;
    cudaGetSymbolAddress(&p, g_x);    float* fX   = (float*)p;
    cudaGetSymbolAddress(&p, g_xmap); float* fXm  = (float*)p;
    cudaGetSymbolAddress(&p, g_b0);   float* fB0  = (float*)p;
    cudaGetSymbolAddress(&p, g_xsp);  float* fXsp = (float*)p;
    cudaGetSymbolAddress(&p, g_eb0);  float* fEb0 = (float*)p;

    cudaFuncSetAttribute(k_gemm<256, 512, 1>, cudaFuncAttributeMaxDynamicSharedMemorySize, SMEM_BYTES);
    cudaFuncSetAttribute(k_gemm<512, 1024, 0>, cudaFuncAttributeMaxDynamicSharedMemorySize, SMEM_BYTES);
    cudaFuncSetAttribute(k_gemm<512, 512, 0>, cudaFuncAttributeMaxDynamicSharedMemorySize, SMEM_BYTES);
    cudaFuncSetAttribute(k_gemm<512, 512, 2>, cudaFuncAttributeMaxDynamicSharedMemorySize, SMEM_BYTES);
    cudaFuncSetAttribute(k_gemm<1024, 512, 3>, cudaFuncAttributeMaxDynamicSharedMemorySize, SMEM_BYTES);

    k_zero<<<1, 32>>>();
    k_prep_R<<<dim3(16, 16), dim3(16, 16)>>>(W, WX);
    k_prepB<<<(131072 + 2 * 524288) / 256, 256>>>(E0, WX);

    // ER[m][k'] = sum_k E[m][k] R[k][k']  -> A = R^T (512 rows), X = E (1024 "batch" rows)
    k_gemm<512, 512, 0><<<dim3(1024 / 128, 512 / 128), 256, SMEM_BYTES>>>(
        fRT, fE, fER, nullptr, nullptr, nullptr, nullptr, nullptr, nullptr, 0);

    // b0 = WXr.y ; x1 = gamma1*b0 (fused)
    k_gemm<256, 512, 1><<<dim3(BB / 128, 4), 256, SMEM_BYTES>>>(
        fWXr, y, fB0, fX, nullptr, nullptr, nullptr, gammas + 1, nullptr, 0);

    // Eb0 = E.b0
    k_gemm<512, 1024, 0><<<dim3(BB / 128, 8), 256, SMEM_BYTES>>>(
        fE, fB0, fEb0, nullptr, nullptr, nullptr, nullptr, nullptr, nullptr, 0);

    k_build_S<<<(9 * 1536 * 512 + 255) / 256, 256>>>(gammas);

    // iteration 1: xsp = shrink(g1*Eb0), then decode
    k_shrink1<<<(int)((size_t)BB * MD / 256), 256>>>(gammas, etas);
    k_gemm<1024, 512, 3><<<dim3(BB / 128, 4), 256, SMEM_BYTES>>>(
        fD, fXsp, fXm, nullptr, fX, nullptr, nullptr, nullptr, nullptr, 0);

    for (int i = 2; i <= TT; i++) {
        const float* Si = fS + (size_t)(i - 2) * 1536 * 512;
        // fused: rows 0-511 -> x ; rows 512-1535 -> xsp (shrink)
        k_gemm<512, 512, 2><<<dim3(BB / 128, 12), 256, SMEM_BYTES>>>(
            Si, fXm, fX, fXsp, nullptr, fB0, fEb0, gammas + i, etas + i, (i == TT) ? 1 : 0);
        // decode + huber
        k_gemm<1024, 512, 3><<<dim3(BB / 128, 4), 256, SMEM_BYTES>>>(
            fD, fXsp, fXm, nullptr, fX, nullptr, nullptr, nullptr, nullptr, 0);
    }
    k_final<<<2 * BB * KD / 256, 256>>>(out);
    k_scalars<<<1, 32>>>(out);
}

// round 13
// speedup vs baseline: 1.0446x; 1.0446x over previous
#include <cuda_runtime.h>
#include <cstdint>
#include <math.h>

#define BB 8192
#define KD 256     // complex dim K
#define MD 1024    // sparse dim M
#define TT 10

#define LDA 36                  // padded smem row stride (floats)
#define ATSZ (128 * LDA)        // A tile floats (4608)
#define XTSZ (64 * LDA)         // X tile floats (2304)
#define STGF (ATSZ + XTSZ)      // per-stage floats (6912)
#define SMEM_BYTES (2 * STGF * 4)   // 55296 B -> 3 CTAs/SM

// ---------------- scratch ----------------
__device__ __align__(16) float g_x[BB * 512];          // x    [b][2K]
__device__ __align__(16) float g_xmap[BB * 512];       // xmap [b][2K]
__device__ __align__(16) float g_b0[BB * 512];         // b0   [b][2K]
__device__ __align__(16) float g_xsp[(size_t)BB * MD]; // xsp  [b][M]
__device__ __align__(16) float g_R[512 * 512];
__device__ __align__(16) float g_WXr[512 * 256];
__device__ __align__(16) float g_E[MD * 512];
__device__ __align__(16) float g_D[512 * MD];
__device__ __align__(16) float g_acc[3];

// ---------------- asm helpers ----------------
__device__ __forceinline__ uint32_t smem_u32(const void* p) {
    uint32_t a;
    asm("{ .reg .u64 t; cvta.to.shared.u64 t, %1; cvt.u32.u64 %0, t; }" : "=r"(a) : "l"(p));
    return a;
}
__device__ __forceinline__ void cp16(uint32_t dst, const void* src) {
    asm volatile("cp.async.cg.shared.global [%0], [%1], 16;" :: "r"(dst), "l"(src));
}
__device__ __forceinline__ void cp_commit() {
    asm volatile("cp.async.commit_group;" ::: "memory");
}
template <int N>
__device__ __forceinline__ void cp_wait() {
    asm volatile("cp.async.wait_group %0;" :: "n"(N) : "memory");
}
__device__ __forceinline__ void mma8(float* c, uint32_t a0, uint32_t a1, uint32_t a2, uint32_t a3,
                                     uint32_t b0, uint32_t b1) {
    asm volatile(
        "mma.sync.aligned.m16n8k8.row.col.f32.tf32.tf32.f32 "
        "{%0,%1,%2,%3}, {%4,%5,%6,%7}, {%8,%9}, {%0,%1,%2,%3};"
        : "+f"(c[0]), "+f"(c[1]), "+f"(c[2]), "+f"(c[3])
        : "r"(a0), "r"(a1), "r"(a2), "r"(a3), "r"(b0), "r"(b1));
}
// hi = rna-tf32(v); lo = raw residual (MMA truncates tail; ~2^-21, negligible)
__device__ __forceinline__ void split1(float v, uint32_t& h, uint32_t& l) {
    uint32_t hb;
    asm("cvt.rna.tf32.f32 %0, %1;" : "=r"(hb) : "f"(v));
    h = hb;
    l = __float_as_uint(v - __uint_as_float(hb));
}

// ---------------- tf32x3 GEMM: D[m][b] = A[m][:] . X[b][:] ----------------
// CTA tile 128(m) x 64(b); 8 warps of 32x32; 3 CTAs/SM -> 6 warps/SMSP.
// EPI: 0 = plain store, 1 = x-update, 2 = shrink(+L1,+count), 3 = xmap(+huber)
template <int KIN, int MOUT, int EPI>
__global__ void __launch_bounds__(256, 3) k_gemm(
    const float* __restrict__ A, const float* __restrict__ Xm, float* __restrict__ OUT,
    const float* __restrict__ aux1, const float* __restrict__ aux2,
    const float* __restrict__ scal, int last)
{
    extern __shared__ float sm[];
    float* As = sm;                 // [2][128][LDA]
    float* Xs = sm + 2 * ATSZ;      // [2][64][LDA]

    const int tid = threadIdx.x;
    const int wid = tid >> 5, lane = tid & 31;
    const int g = lane >> 2, tg = lane & 3;
    const int bb0 = blockIdx.x * 64;
    const int m0 = blockIdx.y * 128;
    const int m_off = (wid & 3) * 32;       // 4 m-tiles of 32
    const int n_off = (wid >> 2) * 32;      // 2 n-tiles of 32

    constexpr int NS = KIN / 32;

    auto issue = [&](int st) {
        const int kk = st * 32;
        float* Ao = As + (st & 1) * ATSZ;
        float* Xo = Xs + (st & 1) * XTSZ;
#pragma unroll
        for (int r = 0; r < 4; r++) {       // A: 1024 float4
            int q = tid + 256 * r;
            int row = q >> 3, cg = (q & 7) * 4;
            cp16(smem_u32(Ao + row * LDA + cg), A + (size_t)(m0 + row) * KIN + kk + cg);
        }
#pragma unroll
        for (int r = 0; r < 2; r++) {       // X: 512 float4
            int q = tid + 256 * r;
            int row = q >> 3, cg = (q & 7) * 4;
            cp16(smem_u32(Xo + row * LDA + cg), Xm + (size_t)(bb0 + row) * KIN + kk + cg);
        }
        cp_commit();
    };

    float c[2][4][4];
#pragma unroll
    for (int i = 0; i < 2; i++)
#pragma unroll
        for (int j = 0; j < 4; j++)
#pragma unroll
            for (int q = 0; q < 4; q++) c[i][j][q] = 0.f;

    issue(0);
    issue(1);

    for (int kt = 0; kt < NS; kt++) {
        cp_wait<1>();
        __syncthreads();

        const float* Ab = As + (kt & 1) * ATSZ;
        const float* Xb = Xs + (kt & 1) * XTSZ;
#pragma unroll
        for (int ks = 0; ks < 4; ks++) {
            const float* ap = Ab + (m_off + g) * LDA + ks * 8 + tg;
            const float* xp = Xb + (n_off + g) * LDA + ks * 8 + tg;
            uint32_t ah[2][4], al[2][4], xh[4][2], xl[4][2];
#pragma unroll
            for (int mf = 0; mf < 2; mf++) {
                split1(ap[mf * 16 * LDA],               ah[mf][0], al[mf][0]);
                split1(ap[mf * 16 * LDA + 8 * LDA],     ah[mf][1], al[mf][1]);
                split1(ap[mf * 16 * LDA + 4],           ah[mf][2], al[mf][2]);
                split1(ap[mf * 16 * LDA + 8 * LDA + 4], ah[mf][3], al[mf][3]);
            }
#pragma unroll
            for (int nf = 0; nf < 4; nf++) {
                split1(xp[nf * 8 * LDA],     xh[nf][0], xl[nf][0]);
                split1(xp[nf * 8 * LDA + 4], xh[nf][1], xl[nf][1]);
            }
#pragma unroll
            for (int mf = 0; mf < 2; mf++)
#pragma unroll
                for (int nf = 0; nf < 4; nf++) {
                    mma8(c[mf][nf], ah[mf][0], ah[mf][1], ah[mf][2], ah[mf][3], xh[nf][0], xh[nf][1]);
                    mma8(c[mf][nf], ah[mf][0], ah[mf][1], ah[mf][2], ah[mf][3], xl[nf][0], xl[nf][1]);
                    mma8(c[mf][nf], al[mf][0], al[mf][1], al[mf][2], al[mf][3], xh[nf][0], xh[nf][1]);
                }
        }
        __syncthreads();
        if (kt + 2 < NS) issue(kt + 2);
        else cp_commit();           // keep group count aligned for cp_wait<1>
    }

    // ---------------- epilogue ----------------
    float s_a = 0.f, s_b = 0.f;
    float gam = 0.f, eta = 0.f;
    if (EPI == 1) gam = scal[0];
    if (EPI == 2) eta = scal[0];
#pragma unroll
    for (int mf = 0; mf < 2; mf++)
#pragma unroll
        for (int nf = 0; nf < 4; nf++) {
#pragma unroll
            for (int q = 0; q < 4; q++) {
                int m = m0 + m_off + mf * 16 + g + (q >= 2 ? 8 : 0);
                int b = bb0 + n_off + nf * 8 + tg * 2 + (q & 1);
                size_t o = (size_t)b * MOUT + m;
                float d = c[mf][nf][q];
                if (EPI == 0) {
                    OUT[o] = d;
                } else if (EPI == 1) {
                    OUT[o] = aux1[o] - gam * (d - aux2[o]);
                } else if (EPI == 2) {
                    float ad = fabsf(d) - eta;
                    float v = (ad > 0.f) ? copysignf(ad, d) : 0.f;
                    OUT[o] = v;
                    s_a += fabsf(v);
                    if (last) s_b += (fabsf(v) > 1e-3f) ? 1.f : 0.f;
                } else {
                    float xo = aux1[o];
                    float dd = xo - d; float ad = fabsf(dd);
                    s_a += (ad < 1.f) ? 0.5f * dd * dd : ad - 0.5f;
                    OUT[o] = d;
                }
            }
        }
    if (EPI == 2 || EPI == 3) {
#pragma unroll
        for (int off = 16; off > 0; off >>= 1) {
            s_a += __shfl_down_sync(0xffffffffu, s_a, off);
            if (EPI == 2) s_b += __shfl_down_sync(0xffffffffu, s_b, off);
        }
        if (lane == 0) {
            atomicAdd(&g_acc[EPI == 2 ? 0 : 1], s_a);
            if (EPI == 2 && last) atomicAdd(&g_acc[2], s_b);
        }
    }
}

// ---------------- prep kernels ----------------
__global__ void k_zero() { if (threadIdx.x < 3) g_acc[threadIdx.x] = 0.f; }

// R = real form of P = WX(2,256,128) @ W(2,128,256)
__global__ void k_prep_R(const float* __restrict__ W, const float* __restrict__ WX) {
    int j = blockIdx.x * 16 + threadIdx.x;   // 0..255
    int i = blockIdx.y * 16 + threadIdx.y;   // 0..255
    float pre = 0.f, pim = 0.f;
#pragma unroll 4
    for (int n = 0; n < 128; n++) {
        float ar = WX[i * 128 + n], ai = WX[32768 + i * 128 + n];
        float br = W[n * 256 + j],  bi = W[32768 + n * 256 + j];
        pre += ar * br - ai * bi;
        pim += ar * bi + ai * br;
    }
    g_R[i * 512 + j] = pre;
    g_R[i * 512 + j + 256] = -pim;
    g_R[(i + 256) * 512 + j] = pim;
    g_R[(i + 256) * 512 + j + 256] = pre;
}

__global__ void k_prep_WXr(const float* __restrict__ WX) {
    int idx = blockIdx.x * 256 + threadIdx.x;          // 512*256
    int np = idx & 255, j = idx >> 8;
    int jj = j & 255, jr = j >> 8;
    int nn = np & 127, nc = np >> 7;
    float re = WX[jj * 128 + nn], im = WX[32768 + jj * 128 + nn];
    float v;
    if (jr == 0) v = (nc == 0) ? re : -im;
    else         v = (nc == 0) ? im :  re;
    g_WXr[idx] = v;
}

__global__ void k_prep_E(const float* __restrict__ E0) {
    int idx = blockIdx.x * 256 + threadIdx.x;          // 1024*512
    int k = idx & 511, mrow = idx >> 9;
    g_E[idx] = (k < 256) ? E0[mrow * 256 + k] : -E0[262144 + mrow * 256 + (k - 256)];
}

__global__ void k_prep_D(const float* __restrict__ E0) {
    int idx = blockIdx.x * 256 + threadIdx.x;          // 512*1024
    int mrow = idx & 1023, j = idx >> 10;
    g_D[idx] = (j < 256) ? E0[mrow * 256 + j] : -E0[262144 + mrow * 256 + (j - 256)];
}

__global__ void k_x1(const float* __restrict__ gammas) {
    int idx = blockIdx.x * 256 + threadIdx.x;          // 8192*512
    g_x[idx] = gammas[1] * g_b0[idx];
}

__global__ void k_final(float* __restrict__ out) {
    int idx = blockIdx.x * 256 + threadIdx.x;          // 2*8192*256
    int k = idx & 255, b = (idx >> 8) & 8191, cch = idx >> 21;
    out[idx] = g_xmap[(size_t)b * 512 + cch * 256 + k];
}

__global__ void k_scalars(float* __restrict__ out) {
    if (threadIdx.x == 0 && blockIdx.x == 0) {
        size_t base = 2ull * BB * KD;
        out[base + 0] = g_acc[0] / (float)BB;
        out[base + 1] = g_acc[1] / ((float)2 * KD * BB * TT);
        out[base + 2] = g_acc[2] / (float)BB;
    }
}

// ---------------- launch ----------------
extern "C" void kernel_launch(void* const* d_in, const int* in_sizes, int n_in,
                              void* d_out, int out_size) {
    const float* y      = (const float*)d_in[0];
    const float* W      = (const float*)d_in[1];
    const float* WX     = (const float*)d_in[2];
    const float* E0     = (const float*)d_in[3];
    const float* etas   = (const float*)d_in[4];
    const float* gammas = (const float*)d_in[5];
    float* out = (float*)d_out;

    void *pR, *pWXr, *pE, *pD, *pX, *pXmap, *pB0, *pXsp;
    cudaGetSymbolAddress(&pR, g_R);
    cudaGetSymbolAddress(&pWXr, g_WXr);
    cudaGetSymbolAddress(&pE, g_E);
    cudaGetSymbolAddress(&pD, g_D);
    cudaGetSymbolAddress(&pX, g_x);
    cudaGetSymbolAddress(&pXmap, g_xmap);
    cudaGetSymbolAddress(&pB0, g_b0);
    cudaGetSymbolAddress(&pXsp, g_xsp);
    const float *fR = (const float*)pR, *fWXr = (const float*)pWXr;
    const float *fE = (const float*)pE, *fD = (const float*)pD;
    float *fX = (float*)pX, *fXmap = (float*)pXmap, *fB0 = (float*)pB0, *fXsp = (float*)pXsp;

    cudaFuncSetAttribute(k_gemm<256, 512, 0>, cudaFuncAttributeMaxDynamicSharedMemorySize, SMEM_BYTES);
    cudaFuncSetAttribute(k_gemm<512, 512, 1>, cudaFuncAttributeMaxDynamicSharedMemorySize, SMEM_BYTES);
    cudaFuncSetAttribute(k_gemm<512, 1024, 2>, cudaFuncAttributeMaxDynamicSharedMemorySize, SMEM_BYTES);
    cudaFuncSetAttribute(k_gemm<1024, 512, 3>, cudaFuncAttributeMaxDynamicSharedMemorySize, SMEM_BYTES);

    k_zero<<<1, 32>>>();
    k_prep_R<<<dim3(16, 16), dim3(16, 16)>>>(W, WX);
    k_prep_WXr<<<512 * 256 / 256, 256>>>(WX);
    k_prep_E<<<1024 * 512 / 256, 256>>>(E0);
    k_prep_D<<<512 * 1024 / 256, 256>>>(E0);

    // b0 = WXr . y   (y is [b][2N] = [b][256] row-major, used raw as X)
    k_gemm<256, 512, 0><<<dim3(BB / 64, 4), 256, SMEM_BYTES>>>(fWXr, y, fB0,
        nullptr, nullptr, nullptr, 0);
    k_x1<<<BB * 512 / 256, 256>>>(gammas);

    for (int i = 1; i <= TT; i++) {
        if (i > 1)
            k_gemm<512, 512, 1><<<dim3(BB / 64, 4), 256, SMEM_BYTES>>>(fR, fXmap, fX,
                fXmap, fB0, gammas + i, 0);
        k_gemm<512, 1024, 2><<<dim3(BB / 64, 8), 256, SMEM_BYTES>>>(fE, fX, fXsp,
            nullptr, nullptr, etas + i, (i == TT) ? 1 : 0);
        k_gemm<1024, 512, 3><<<dim3(BB / 64, 4), 256, SMEM_BYTES>>>(fD, fXsp, fXmap,
            fX, nullptr, nullptr, 0);
    }
    k_final<<<2 * BB * KD / 256, 256>>>(out);
    k_scalars<<<1, 32>>>(out);
}

// round 14
// speedup vs baseline: 1.1138x; 1.0663x over previous
#include <cuda_runtime.h>
#include <cstdint>
#include <math.h>

#define BB 8192
#define KD 256     // complex dim K
#define MD 1024    // sparse dim M
#define TT 10

#define LDA 36               // padded smem row stride (floats)
#define TSZ (128 * LDA)      // one tile (floats)
#define SMEM_FLOATS (6 * TSZ)          // A/X x 3 stages
#define SMEM_BYTES (SMEM_FLOATS * 4)   // 110592

// ---------------- scratch ----------------
__device__ __align__(16) float g_x[BB * 512];          // x    [b][2K]
__device__ __align__(16) float g_xmap[BB * 512];       // xmap [b][2K]
__device__ __align__(16) float g_b0[BB * 512];         // b0   [b][2K]
__device__ __align__(16) float g_xsp[(size_t)BB * MD]; // xsp  [b][M]
__device__ __align__(16) float g_R[512 * 512];
__device__ __align__(16) float g_WXr[512 * 256];
__device__ __align__(16) float g_E[MD * 512];
__device__ __align__(16) float g_D[512 * MD];
__device__ __align__(16) float g_acc[3];

// ---------------- asm helpers ----------------
__device__ __forceinline__ uint32_t smem_u32(const void* p) {
    uint32_t a;
    asm("{ .reg .u64 t; cvta.to.shared.u64 t, %1; cvt.u32.u64 %0, t; }" : "=r"(a) : "l"(p));
    return a;
}
__device__ __forceinline__ void cp16(uint32_t dst, const void* src) {
    asm volatile("cp.async.cg.shared.global [%0], [%1], 16;" :: "r"(dst), "l"(src));
}
__device__ __forceinline__ void cp_commit() {
    asm volatile("cp.async.commit_group;" ::: "memory");
}
template <int N>
__device__ __forceinline__ void cp_wait() {
    asm volatile("cp.async.wait_group %0;" :: "n"(N) : "memory");
}
__device__ __forceinline__ void mma8(float* c, uint32_t a0, uint32_t a1, uint32_t a2, uint32_t a3,
                                     uint32_t b0, uint32_t b1) {
    asm volatile(
        "mma.sync.aligned.m16n8k8.row.col.f32.tf32.tf32.f32 "
        "{%0,%1,%2,%3}, {%4,%5,%6,%7}, {%8,%9}, {%0,%1,%2,%3};"
        : "+f"(c[0]), "+f"(c[1]), "+f"(c[2]), "+f"(c[3])
        : "r"(a0), "r"(a1), "r"(a2), "r"(a3), "r"(b0), "r"(b1));
}
// hi = rna-tf32(v); lo = raw residual (MMA truncates tail; ~2^-21, negligible)
__device__ __forceinline__ void split1(float v, uint32_t& h, uint32_t& l) {
    uint32_t hb;
    asm("cvt.rna.tf32.f32 %0, %1;" : "=r"(hb) : "f"(v));
    h = hb;
    l = __float_as_uint(v - __uint_as_float(hb));
}

// ---------------- tf32x3 GEMM: D[m][b] = A[m][:] . X[b][:] ----------------
// 3-stage smem ring, ONE __syncthreads per stage.
// EPI: 0 = b0 + x1 fused, 1 = x-update, 2 = shrink(+L1,+count), 3 = xmap(+huber)
template <int KIN, int MOUT, int EPI>
__global__ void __launch_bounds__(256, 2) k_gemm(
    const float* __restrict__ A, const float* __restrict__ Xm,
    float* __restrict__ OUT, float* __restrict__ OUT2,
    const float* __restrict__ aux1, const float* __restrict__ aux2,
    const float* __restrict__ scal, int last)
{
    extern __shared__ float sm[];
    float* As = sm;             // [3][128][LDA]
    float* Xs = sm + 3 * TSZ;   // [3][128][LDA]

    const int tid = threadIdx.x;
    const int wid = tid >> 5, lane = tid & 31;
    const int g = lane >> 2, tg = lane & 3;
    const int b0 = blockIdx.x * 128;
    const int m0 = blockIdx.y * 128;
    const int m_off = (wid & 1) * 64;
    const int n_off = (wid >> 1) * 32;

    constexpr int NS = KIN / 32;

    const int crow = tid >> 3, ccg = (tid & 7) * 4;   // copy indexing

    // issue stage st -> buf st%3
    auto issue = [&](int st) {
        const int kk = st * 32;
        const int buf = st % 3;
        float* Ao = As + buf * TSZ;
        float* Xo = Xs + buf * TSZ;
#pragma unroll
        for (int r = 0; r < 4; r++) {
            int rr = crow + 32 * r;
            cp16(smem_u32(Ao + rr * LDA + ccg), A + (size_t)(m0 + rr) * KIN + kk + ccg);
            cp16(smem_u32(Xo + rr * LDA + ccg), Xm + (size_t)(b0 + rr) * KIN + kk + ccg);
        }
        cp_commit();
    };

    float c[4][4][4];
#pragma unroll
    for (int i = 0; i < 4; i++)
#pragma unroll
        for (int j = 0; j < 4; j++)
#pragma unroll
            for (int q = 0; q < 4; q++) c[i][j][q] = 0.f;

    issue(0);
    issue(1);

    for (int kt = 0; kt < NS; kt++) {
        cp_wait<1>();
        __syncthreads();           // all warps done with buf (kt-1)%3; group kt resident

        const int buf = kt % 3;
        const float* Ab = As + buf * TSZ;
        const float* Xb = Xs + buf * TSZ;
#pragma unroll
        for (int ks = 0; ks < 4; ks++) {
            const float* ap = Ab + (m_off + g) * LDA + ks * 8 + tg;
            const float* xp = Xb + (n_off + g) * LDA + ks * 8 + tg;
            uint32_t ah[4][4], al[4][4], xh[4][2], xl[4][2];
#pragma unroll
            for (int mf = 0; mf < 4; mf++) {
                split1(ap[mf * 16 * LDA],               ah[mf][0], al[mf][0]);
                split1(ap[mf * 16 * LDA + 8 * LDA],     ah[mf][1], al[mf][1]);
                split1(ap[mf * 16 * LDA + 4],           ah[mf][2], al[mf][2]);
                split1(ap[mf * 16 * LDA + 8 * LDA + 4], ah[mf][3], al[mf][3]);
            }
#pragma unroll
            for (int nf = 0; nf < 4; nf++) {
                split1(xp[nf * 8 * LDA],     xh[nf][0], xl[nf][0]);
                split1(xp[nf * 8 * LDA + 4], xh[nf][1], xl[nf][1]);
            }
#pragma unroll
            for (int mf = 0; mf < 4; mf++)
#pragma unroll
                for (int nf = 0; nf < 4; nf++) {
                    mma8(c[mf][nf], ah[mf][0], ah[mf][1], ah[mf][2], ah[mf][3], xh[nf][0], xh[nf][1]);
                    mma8(c[mf][nf], ah[mf][0], ah[mf][1], ah[mf][2], ah[mf][3], xl[nf][0], xl[nf][1]);
                    mma8(c[mf][nf], al[mf][0], al[mf][1], al[mf][2], al[mf][3], xh[nf][0], xh[nf][1]);
                }
        }
        // no second barrier: issue(kt+2) writes buf (kt-1)%3, released by this
        // iteration's top barrier (all warps finished computing it at kt-1).
        if (kt + 2 < NS) issue(kt + 2);
        else cp_commit();           // keep group count aligned for cp_wait<1>
    }

    // ---------------- epilogue ----------------
    float s_a = 0.f, s_b = 0.f;
    float gam = 0.f, eta = 0.f;
    if (EPI == 0 || EPI == 1) gam = scal[0];
    if (EPI == 2) eta = scal[0];
#pragma unroll
    for (int mf = 0; mf < 4; mf++)
#pragma unroll
        for (int nf = 0; nf < 4; nf++) {
#pragma unroll
            for (int q = 0; q < 4; q++) {
                int m = m0 + m_off + mf * 16 + g + (q >= 2 ? 8 : 0);
                int b = b0 + n_off + nf * 8 + tg * 2 + (q & 1);
                size_t o = (size_t)b * MOUT + m;
                float d = c[mf][nf][q];
                if (EPI == 0) {
                    OUT[o] = d;             // b0
                    OUT2[o] = gam * d;      // x1 = gamma1 * b0
                } else if (EPI == 1) {
                    OUT[o] = aux1[o] - gam * (d - aux2[o]);
                } else if (EPI == 2) {
                    float ad = fabsf(d) - eta;
                    float v = (ad > 0.f) ? copysignf(ad, d) : 0.f;
                    OUT[o] = v;
                    s_a += fabsf(v);
                    if (last) s_b += (fabsf(v) > 1e-3f) ? 1.f : 0.f;
                } else {
                    float xo = aux1[o];
                    float dd = xo - d; float ad = fabsf(dd);
                    s_a += (ad < 1.f) ? 0.5f * dd * dd : ad - 0.5f;
                    OUT[o] = d;
                }
            }
        }
    if (EPI == 2 || EPI == 3) {
#pragma unroll
        for (int off = 16; off > 0; off >>= 1) {
            s_a += __shfl_down_sync(0xffffffffu, s_a, off);
            if (EPI == 2) s_b += __shfl_down_sync(0xffffffffu, s_b, off);
        }
        if (lane == 0) {
            atomicAdd(&g_acc[EPI == 2 ? 0 : 1], s_a);
            if (EPI == 2 && last) atomicAdd(&g_acc[2], s_b);
        }
    }
}

// ---------------- prep kernels ----------------
// R + acc zero
__global__ void k_prep_R(const float* __restrict__ W, const float* __restrict__ WX) {
    int j = blockIdx.x * 16 + threadIdx.x;   // 0..255
    int i = blockIdx.y * 16 + threadIdx.y;   // 0..255
    if (i == 0 && j < 3) g_acc[j] = 0.f;
    float pre = 0.f, pim = 0.f;
#pragma unroll 4
    for (int n = 0; n < 128; n++) {
        float ar = WX[i * 128 + n], ai = WX[32768 + i * 128 + n];
        float br = W[n * 256 + j],  bi = W[32768 + n * 256 + j];
        pre += ar * br - ai * bi;
        pim += ar * bi + ai * br;
    }
    g_R[i * 512 + j] = pre;
    g_R[i * 512 + j + 256] = -pim;
    g_R[(i + 256) * 512 + j] = pim;
    g_R[(i + 256) * 512 + j + 256] = pre;
}

// WXr / E / D in one grid-stride kernel
__global__ void k_prepB(const float* __restrict__ E0, const float* __restrict__ WX) {
    size_t idx = (size_t)blockIdx.x * 256 + threadIdx.x;
    if (idx < 131072) {                           // WXr [512][256]
        int np = (int)idx & 255, j = (int)idx >> 8;
        int jj = j & 255, jr = j >> 8;
        int nn = np & 127, nc = np >> 7;
        float re = WX[jj * 128 + nn], im = WX[32768 + jj * 128 + nn];
        g_WXr[idx] = (jr == 0) ? ((nc == 0) ? re : -im) : ((nc == 0) ? im : re);
    } else if (idx < 131072 + 524288) {           // E [1024][512]
        size_t t = idx - 131072;
        int k = (int)t & 511, mrow = (int)(t >> 9);
        g_E[t] = (k < 256) ? E0[mrow * 256 + k] : -E0[262144 + mrow * 256 + (k - 256)];
    } else {                                      // D [512][1024]
        size_t t = idx - 131072 - 524288;
        int mrow = (int)t & 1023, j = (int)(t >> 10);
        g_D[t] = (j < 256) ? E0[mrow * 256 + j] : -E0[262144 + mrow * 256 + (j - 256)];
    }
}

__global__ void k_final(float* __restrict__ out) {
    int idx = blockIdx.x * 256 + threadIdx.x;          // 2*8192*256
    int k = idx & 255, b = (idx >> 8) & 8191, cch = idx >> 21;
    out[idx] = g_xmap[(size_t)b * 512 + cch * 256 + k];
}

__global__ void k_scalars(float* __restrict__ out) {
    if (threadIdx.x == 0 && blockIdx.x == 0) {
        size_t base = 2ull * BB * KD;
        out[base + 0] = g_acc[0] / (float)BB;
        out[base + 1] = g_acc[1] / ((float)2 * KD * BB * TT);
        out[base + 2] = g_acc[2] / (float)BB;
    }
}

// ---------------- launch ----------------
extern "C" void kernel_launch(void* const* d_in, const int* in_sizes, int n_in,
                              void* d_out, int out_size) {
    const float* y      = (const float*)d_in[0];
    const float* W      = (const float*)d_in[1];
    const float* WX     = (const float*)d_in[2];
    const float* E0     = (const float*)d_in[3];
    const float* etas   = (const float*)d_in[4];
    const float* gammas = (const float*)d_in[5];
    float* out = (float*)d_out;

    void *p;
    cudaGetSymbolAddress(&p, g_R);    const float* fR   = (const float*)p;
    cudaGetSymbolAddress(&p, g_WXr);  const float* fWXr = (const float*)p;
    cudaGetSymbolAddress(&p, g_E);    const float* fE   = (const float*)p;
    cudaGetSymbolAddress(&p, g_D);    const float* fD   = (const float*)p;
    cudaGetSymbolAddress(&p, g_x);    float* fX   = (float*)p;
    cudaGetSymbolAddress(&p, g_xmap); float* fXm  = (float*)p;
    cudaGetSymbolAddress(&p, g_b0);   float* fB0  = (float*)p;
    cudaGetSymbolAddress(&p, g_xsp);  float* fXsp = (float*)p;

    cudaFuncSetAttribute(k_gemm<256, 512, 0>, cudaFuncAttributeMaxDynamicSharedMemorySize, SMEM_BYTES);
    cudaFuncSetAttribute(k_gemm<512, 512, 1>, cudaFuncAttributeMaxDynamicSharedMemorySize, SMEM_BYTES);
    cudaFuncSetAttribute(k_gemm<512, 1024, 2>, cudaFuncAttributeMaxDynamicSharedMemorySize, SMEM_BYTES);
    cudaFuncSetAttribute(k_gemm<1024, 512, 3>, cudaFuncAttributeMaxDynamicSharedMemorySize, SMEM_BYTES);

    k_prep_R<<<dim3(16, 16), dim3(16, 16)>>>(W, WX);
    k_prepB<<<(131072 + 2 * 524288) / 256, 256>>>(E0, WX);

    // b0 = WXr.y ; x1 = gamma1*b0 (fused)
    k_gemm<256, 512, 0><<<dim3(BB / 128, 4), 256, SMEM_BYTES>>>(
        fWXr, y, fB0, fX, nullptr, nullptr, gammas + 1, 0);

    for (int i = 1; i <= TT; i++) {
        if (i > 1)
            k_gemm<512, 512, 1><<<dim3(BB / 128, 4), 256, SMEM_BYTES>>>(
                fR, fXm, fX, nullptr, fXm, fB0, gammas + i, 0);
        k_gemm<512, 1024, 2><<<dim3(BB / 128, 8), 256, SMEM_BYTES>>>(
            fE, fX, fXsp, nullptr, nullptr, nullptr, etas + i, (i == TT) ? 1 : 0);
        k_gemm<1024, 512, 3><<<dim3(BB / 128, 4), 256, SMEM_BYTES>>>(
            fD, fXsp, fXm, nullptr, fX, nullptr, nullptr, 0);
    }
    k_final<<<2 * BB * KD / 256, 256>>>(out);
    k_scalars<<<1, 32>>>(out);
}